// round 1
// baseline (speedup 1.0000x reference)
#include <cuda_runtime.h>

// MultiLevelAlignedRoIPooling
// feat2: (2,256,256,256) f32   feat3: (2,128,128,256)
// feat4: (2, 64, 64,256)       feat5: (2, 32, 32,256)
// boxes: (2,512,4)  -> out: (2,512,7,7,256) f32

#define PP 7
#define CC 256
#define NB 512
#define BB 2

__global__ __launch_bounds__(256, 8)
void roi_align_kernel(const float* __restrict__ f2,
                      const float* __restrict__ f3,
                      const float* __restrict__ f4,
                      const float* __restrict__ f5,
                      const float* __restrict__ boxes,
                      float* __restrict__ out)
{
    // block = one (b, n, py)
    int blk = blockIdx.x;
    int py  = blk % PP;
    int bn  = blk / PP;          // b*NB + n
    int b   = bn / NB;

    // ---- box scalars (redundant per-thread, cheap) ----
    const float4 bx4 = ((const float4*)boxes)[bn];
    float y1 = bx4.x, x1 = bx4.y, y2 = bx4.z, x2 = bx4.w;
    float bh = y2 - y1, bw = x2 - x1;
    float area_sqrt = sqrtf(bh * bw);
    // match reference: floor(log(a/224)/log(2)) + 4, clipped [2,5]
    int lv = (int)floorf(logf(area_sqrt / 224.0f) / logf(2.0f)) + 4;
    lv = min(max(lv, 2), 5);
    int li = lv - 2;
    float inv_scale = exp2f(-(float)lv);

    float ry1 = y1 * inv_scale - 0.5f;
    float rx1 = x1 * inv_scale - 0.5f;
    float ry2 = y2 * inv_scale - 0.5f;
    float rx2 = x2 * inv_scale - 0.5f;
    float rh = ry2 - ry1, rw = rx2 - rx1;

    int Hl = 256 >> li;                 // = Wl (square levels)
    float bnd = (float)Hl - 1.0f;

    // vertical sample for this py
    float gy  = fminf(ry1 + (float)py * (rh / (float)PP), bnd);
    float y0f = floorf(gy);
    float ly  = gy - y0f;
    float hy  = 1.0f - ly;
    int   y0  = (int)y0f;
    int   y1i = min(y0 + 1, Hl - 1);    // clamp: weight ly==0 whenever clamped

    const float* f = (li == 0) ? f2 : (li == 1) ? f3 : (li == 2) ? f4 : f5;
    const float* fb = f + (size_t)b * Hl * Hl * CC;
    const float4* __restrict__ row0 = (const float4*)(fb + (size_t)y0  * Hl * CC);
    const float4* __restrict__ row1 = (const float4*)(fb + (size_t)y1i * Hl * CC);

    float4* __restrict__ outp = (float4*)(out + (((size_t)bn * PP + py) * PP) * CC);

    int t   = threadIdx.x;
    int c4  = t & 63;        // float4 index within channel dim (256/4 = 64)
    int px0 = t >> 6;        // 0..3

    float rwp = rw / (float)PP;

    #pragma unroll
    for (int pass = 0; pass < 2; ++pass) {
        int px = px0 + pass * 4;
        if (px < PP) {
            float gx  = fminf(rx1 + (float)px * rwp, bnd);
            float x0f = floorf(gx);
            float lx  = gx - x0f;
            float hx  = 1.0f - lx;
            int   x0  = (int)x0f;
            int   x1i = min(x0 + 1, Hl - 1);

            float w00 = hy * hx, w01 = hy * lx, w10 = ly * hx, w11 = ly * lx;

            const float4 a = __ldg(&row0[(size_t)x0  * 64 + c4]);
            const float4 bq= __ldg(&row0[(size_t)x1i * 64 + c4]);
            const float4 cq= __ldg(&row1[(size_t)x0  * 64 + c4]);
            const float4 dq= __ldg(&row1[(size_t)x1i * 64 + c4]);

            float4 r;
            r.x = w00*a.x + w01*bq.x + w10*cq.x + w11*dq.x;
            r.y = w00*a.y + w01*bq.y + w10*cq.y + w11*dq.y;
            r.z = w00*a.z + w01*bq.z + w10*cq.z + w11*dq.z;
            r.w = w00*a.w + w01*bq.w + w10*cq.w + w11*dq.w;

            outp[(size_t)px * 64 + c4] = r;
        }
    }
}

extern "C" void kernel_launch(void* const* d_in, const int* in_sizes, int n_in,
                              void* d_out, int out_size)
{
    const float* f2    = (const float*)d_in[0];
    const float* f3    = (const float*)d_in[1];
    const float* f4    = (const float*)d_in[2];
    const float* f5    = (const float*)d_in[3];
    const float* boxes = (const float*)d_in[4];
    float* out = (float*)d_out;

    dim3 grid(BB * NB * PP);   // 7168 blocks, one per (b,n,py)
    dim3 block(256);
    roi_align_kernel<<<grid, block>>>(f2, f3, f4, f5, boxes, out);
}